// round 9
// baseline (speedup 1.0000x reference)
#include <cuda_runtime.h>
#include <math.h>

#define BB 64
#define NN 17
#define CC 32
#define HW 4096   // 64*64
#define TR 8      // rows per tile

#define OFF_J 0           // joints: 64*17*2 = 2176
#define OFF_V 2176        // valid:  64*17   = 1088
#define OFF_K 3264        // new_keys: 64*17*32 = 34816
#define OFF_D 38080       // dist_x4: 64*17*256*256 = 71303168

// packed (float_bits<<32 | idx) argmin scratch; v>=0 so bits are monotone.
__device__ unsigned long long g_m1[BB * NN];   // wdist argmin (64x64)
__device__ unsigned long long g_m2[BB * NN];   // dist_x4 argmin (256x256)

__global__ void kInit() {
    int i = blockIdx.x * 256 + threadIdx.x;
    if (i < BB * NN) { g_m1[i] = ~0ull; g_m2[i] = ~0ull; }
}

// Analytic weight map (empirically identical to the literal 15-move loop)
__device__ __forceinline__ float weight_at(int x, int y, int kx, int ky) {
    int dx = abs(x - kx), dy = abs(y - ky);
    int m = 0;
    int mc = (dx > 0) ? dx : ((kx == 0 || kx == 63) ? 1 : 0);
    if (mc >= 1 && mc <= 15 && dy <= mc) m = mc;
    int mr = (dy > 0) ? dy : ((ky == 0 || ky == 63) ? 1 : 0);
    if (mr >= 1 && mr <= 15 && dx <= mr && mr > m) m = mr;
    return m ? (0.5f + 0.25f * (float)m) : 10.0f;
}

// One pixel's 17 wdist values -> smem row lr. Bit-exact identical sequence
// regardless of which block executes it (halo duplicates are exact).
__device__ __forceinline__ void dist_row(const float* __restrict__ q, int b,
        int gy, int col, int lr,
        const float (*skey)[CC], const float* __restrict__ sk2,
        const int* __restrict__ skx, const int* __restrict__ sky,
        float (*sw)[TR + 2][64])
{
    const float* qb = q + (size_t)b * CC * HW + gy * 64 + col;
    float qv[CC];
    float q2 = 0.f;
#pragma unroll
    for (int c = 0; c < CC; c++) {
        qv[c] = qb[(size_t)c * HW];
        q2 = __fadd_rn(q2, __fmul_rn(qv[c], qv[c]));   // mul+add, no fma
    }
#pragma unroll 1
    for (int n = 0; n < NN; n++) {
        const float4* k4 = (const float4*)skey[n];
        float dot = 0.f;   // sequential ascending-c fmaf (gemm-faithful)
#pragma unroll
        for (int c4 = 0; c4 < CC / 4; c4++) {
            float4 kk = k4[c4];
            dot = fmaf(kk.x, qv[4 * c4 + 0], dot);
            dot = fmaf(kk.y, qv[4 * c4 + 1], dot);
            dot = fmaf(kk.z, qv[4 * c4 + 2], dot);
            dot = fmaf(kk.w, qv[4 * c4 + 3], dot);
        }
        float d2 = __fsub_rn(__fadd_rn(q2, sk2[n]), __fmul_rn(2.0f, dot));
        float dist = sqrtf(fmaxf(d2, 0.0f));
        sw[n][lr][col] = __fmul_rn(dist, weight_at(col, gy, skx[n], sky[n]));
    }
}

// ---------------- Fused kernel: dist + upsample + packed argmins ----------
__global__ void __launch_bounds__(512) kFused(const float* __restrict__ q,
                                              const float* __restrict__ keys,
                                              const int*   __restrict__ joints,
                                              float* __restrict__ out)
{
    const int b  = blockIdx.y;
    const int r0 = blockIdx.x * TR;
    const int t  = threadIdx.x;

    __shared__ __align__(16) float skey[NN][CC];
    __shared__ float sk2[NN];
    __shared__ int   skx[NN], sky[NN];
    __shared__ float sw[NN][TR + 2][64];   // [n][local row 0..9][col]

    if (t < NN * CC / 4)
        ((float4*)skey)[t] = ((const float4*)(keys + b * NN * CC))[t];
    __syncthreads();
    if (t < NN) {
        float s = 0.f;   // mul+add sequential, no fma (XLA-faithful)
        for (int c = 0; c < CC; c++) s = __fadd_rn(s, __fmul_rn(skey[t][c], skey[t][c]));
        sk2[t] = s;
        skx[t] = joints[(b * NN + t) * 2 + 0];
        sky[t] = joints[(b * NN + t) * 2 + 1];
    }
    __syncthreads();

    // halo rows (exact duplicates of neighbor blocks' main rows)
    if (t < 64) {
        if (r0 > 0) dist_row(q, b, r0 - 1, t, 0, skey, sk2, skx, sky, sw);
    } else if (t < 128) {
        if (r0 + TR < 64) dist_row(q, b, r0 + TR, t - 64, TR + 1, skey, sk2, skx, sky, sw);
    }
    // main rows
    const int lrow = t >> 6;        // 0..7
    const int col  = t & 63;
    const int gy   = r0 + lrow;
    const int lti  = lrow + 1;      // 1..8
    dist_row(q, b, gy, col, lti, skey, sk2, skx, sky, sw);
    __syncthreads();

    const int pix = gy * 64 + col;
    float* od_base = out + OFF_D + (size_t)(b * NN) * 65536;

#pragma unroll 1
    for (int n = 0; n < NN; n++) {
        // ---- phase-1 argmin (wdist): warp reduce + atomic ----
        {
            float v = sw[n][lti][col];
            unsigned long long pk =
                ((unsigned long long)__float_as_uint(v) << 32) | (unsigned)pix;
#pragma unroll
            for (int o = 16; o; o >>= 1) {
                unsigned long long p2 = __shfl_down_sync(0xffffffffu, pk, o);
                pk = (p2 < pk) ? p2 : pk;
            }
            if ((t & 31) == 0) atomicMin(&g_m1[b * NN + n], pk);
        }

        // ---- upsample 4x4 for this pixel (round-6 verified arithmetic) ----
        const float* rC = sw[n][lti];
        const float* rU = sw[n][(gy > 0)  ? lti - 1 : lti];
        const float* rD = sw[n][(gy < 63) ? lti + 1 : lti];
        const int xL = (col > 0)  ? col - 1 : 0;
        const int xR = (col < 63) ? col + 1 : 63;

        float up[3] = { rU[xL], rU[col], rU[xR] };
        float ce[3] = { rC[xL], rC[col], rC[xR] };
        float dn[3] = { rD[xL], rD[col], rD[xR] };

        float vy[4][3];
#pragma unroll
        for (int c3 = 0; c3 < 3; c3++) {
            if (gy == 0) { vy[0][c3] = ce[c3]; vy[1][c3] = ce[c3]; }
            else {
                vy[0][c3] = fmaf(0.625f, ce[c3], __fmul_rn(0.375f, up[c3]));
                vy[1][c3] = fmaf(0.875f, ce[c3], __fmul_rn(0.125f, up[c3]));
            }
            if (gy == 63) { vy[2][c3] = ce[c3]; vy[3][c3] = ce[c3]; }
            else {
                vy[2][c3] = fmaf(0.125f, dn[c3], __fmul_rn(0.875f, ce[c3]));
                vy[3][c3] = fmaf(0.375f, dn[c3], __fmul_rn(0.625f, ce[c3]));
            }
        }

        float* od = od_base + (size_t)n * 65536;
        float  bv = 3.0e38f;
        float4 bqv = make_float4(0.f, 0.f, 0.f, 0.f);
        int    bqb = 0;
#pragma unroll
        for (int r = 0; r < 4; r++) {
            float vL = vy[r][0], vC = vy[r][1], vR = vy[r][2];
            float o0, o1, o2, o3;
            if (col == 0) { o0 = vC; o1 = vC; }
            else {
                o0 = fmaf(0.625f, vC, __fmul_rn(0.375f, vL));
                o1 = fmaf(0.875f, vC, __fmul_rn(0.125f, vL));
            }
            if (col == 63) { o2 = vC; o3 = vC; }
            else {
                o2 = fmaf(0.125f, vR, __fmul_rn(0.875f, vC));
                o3 = fmaf(0.375f, vR, __fmul_rn(0.625f, vC));
            }
            float4 o4 = make_float4(o0, o1, o2, o3);
            int pbase = (4 * gy + r) * 256 + 4 * col;
            *reinterpret_cast<float4*>(od + pbase) = o4;
            float qm = fminf(fminf(o0, o1), fminf(o2, o3));
            if (qm < bv) { bv = qm; bqv = o4; bqb = pbase; }   // ascending r
        }
        // resolve first element inside the winning quad
        int ei = bqb + ((bqv.x == bv) ? 0 : (bqv.y == bv) ? 1 : (bqv.z == bv) ? 2 : 3);
        unsigned long long pk =
            ((unsigned long long)__float_as_uint(bv) << 32) | (unsigned)ei;
#pragma unroll
        for (int o = 16; o; o >>= 1) {
            unsigned long long p2 = __shfl_down_sync(0xffffffffu, pk, o);
            pk = (p2 < pk) ? p2 : pk;
        }
        if ((t & 31) == 0) atomicMin(&g_m2[b * NN + n], pk);
    }
}

// ---------------- Epilogue: joints / valid / new_keys ----------------
__global__ void __launch_bounds__(1024) kF(const float* __restrict__ q,
                                           const float* __restrict__ keys,
                                           float* __restrict__ out)
{
    int w = blockIdx.x * 32 + (threadIdx.x >> 5);   // bn, 34*32 = 1088 exact
    int lane = threadIdx.x & 31;
    int b = w / NN;

    unsigned long long m1 = g_m1[w];
    unsigned long long m2 = g_m2[w];
    float gmin1 = __uint_as_float((unsigned)(m1 >> 32));
    int   idx1  = (int)(m1 & 0xffffffffu);
    int   sidx  = (int)(m2 & 0xffffffffu);

    float kv = keys[w * CC + lane];
    bool nz = __any_sync(0xffffffffu, kv != 0.0f);
    bool valid = nz && ((int)floorf(gmin1) <= 5);

    if (lane == 0) {
        int sv = valid ? (sidx >> 8)  : -1;
        int sh = valid ? (sidx & 255) : -1;
        out[OFF_J + w * 2 + 0] = (float)sv;
        out[OFF_J + w * 2 + 1] = (float)sh;
        out[OFF_V + w] = valid ? 1.0f : 0.0f;
    }
    out[OFF_K + w * CC + lane] =
        valid ? q[((size_t)b * CC + lane) * HW + idx1] : kv;
}

extern "C" void kernel_launch(void* const* d_in, const int* in_sizes, int n_in,
                              void* d_out, int out_size) {
    const float* q      = (const float*)d_in[0];
    const float* keys   = (const float*)d_in[1];
    const int*   joints = (const int*)  d_in[2];
    float* out = (float*)d_out;

    kInit<<<(BB * NN + 255) / 256, 256>>>();
    dim3 g(64 / TR, BB);
    kFused<<<g, 512>>>(q, keys, joints, out);
    kF<<<34, 1024>>>(q, keys, out);
}